// round 12
// baseline (speedup 1.0000x reference)
#include <cuda_runtime.h>
#include <cuda_fp16.h>
#include <cstdint>

#define NMAX 100000
#define CAP 64         // per-dst bucket capacity (max degree ~40 for Poisson(16))
#define RS 272         // smem row stride bytes (136 halves) -> conflict-free ldmatrix
#define RSH 136
#define BUF 34816      // 128 * RS

__device__ __align__(256) __half g_h16[(size_t)NMAX * 128];
__device__ __align__(256) __half g_agg16[(size_t)NMAX * 128];
__device__ __align__(256) __half g_wenc16[128 * RSH];
__device__ __align__(256) __half g_w1h[2][128 * RSH];
__device__ __align__(256) __half g_w2h[2][128 * RSH];
__device__ int g_cnt[NMAX];
__device__ int g_sorted[(size_t)NMAX * CAP];

// ---------------------------------------------------------------------------
__device__ __forceinline__ uint32_t smem_u32(const void* p) {
    uint32_t a;
    asm("{ .reg .u64 t; cvta.to.shared.u64 t, %1; cvt.u32.u64 %0, t; }"
        : "=r"(a) : "l"(p));
    return a;
}
__device__ __forceinline__ void ldsm4(uint32_t* r, uint32_t addr) {
    asm volatile("ldmatrix.sync.aligned.m8n8.x4.shared.b16 {%0,%1,%2,%3}, [%4];"
                 : "=r"(r[0]), "=r"(r[1]), "=r"(r[2]), "=r"(r[3]) : "r"(addr));
}
__device__ __forceinline__ void mma_f16(float* c, const uint32_t* a, const uint32_t* b) {
    asm volatile(
        "mma.sync.aligned.m16n8k16.row.col.f32.f16.f16.f32 "
        "{%0,%1,%2,%3}, {%4,%5,%6,%7}, {%8,%9}, {%0,%1,%2,%3};"
        : "+f"(c[0]), "+f"(c[1]), "+f"(c[2]), "+f"(c[3])
        : "r"(a[0]), "r"(a[1]), "r"(a[2]), "r"(a[3]), "r"(b[0]), "r"(b[1]));
}
__device__ __forceinline__ void cp16(uint32_t smem_dst, const void* gsrc) {
    asm volatile("cp.async.cg.shared.global [%0], [%1], 16;"
                 :: "r"(smem_dst), "l"(gsrc));
}
__device__ __forceinline__ void cp_commit_wait() {
    asm volatile("cp.async.commit_group;");
    asm volatile("cp.async.wait_group 0;" ::: "memory");
}
__device__ __forceinline__ uint4 cvt_h8(const float* v) {
    __half2 h0 = __floats2half2_rn(v[0], v[1]);
    __half2 h1 = __floats2half2_rn(v[2], v[3]);
    __half2 h2 = __floats2half2_rn(v[4], v[5]);
    __half2 h3 = __floats2half2_rn(v[6], v[7]);
    return make_uint4(*reinterpret_cast<uint32_t*>(&h0),
                      *reinterpret_cast<uint32_t*>(&h1),
                      *reinterpret_cast<uint32_t*>(&h2),
                      *reinterpret_cast<uint32_t*>(&h3));
}

// single-term fp16 K=128 GEMM, 16-warp layout: acc[2][4][4], 32x32 warp tile
__device__ __forceinline__ void gemm_k128_f16(
    float acc[2][4][4], uint32_t sA, uint32_t sB, int wm, int wn, int lane)
{
    const int arow = lane & 15;
    const int akc  = (lane >> 4) * 8;
    const int bn   = (lane & 7) + (lane >> 4) * 8;
    const int bk   = ((lane >> 3) & 1) * 8;
#pragma unroll
    for (int ks = 0; ks < 8; ks++) {
        const int k0 = ks * 16;
        uint32_t a[2][4];
#pragma unroll
        for (int mf = 0; mf < 2; mf++)
            ldsm4(a[mf], sA + (uint32_t)(wm + mf * 16 + arow) * RS + (uint32_t)(k0 + akc) * 2);
        uint32_t b[4][2];
#pragma unroll
        for (int g = 0; g < 2; g++) {
            uint32_t r[4];
            ldsm4(r, sB + (uint32_t)(wn + g * 16 + bn) * RS + (uint32_t)(k0 + bk) * 2);
            b[2 * g][0] = r[0]; b[2 * g][1] = r[1];
            b[2 * g + 1][0] = r[2]; b[2 * g + 1][1] = r[3];
        }
#pragma unroll
        for (int mf = 0; mf < 2; mf++)
#pragma unroll
            for (int nf = 0; nf < 4; nf++)
                mma_f16(acc[mf][nf], a[mf], b[nf]);
    }
}

// ---------------------------------------------------------------------------
// prep+zero: blocks 0-4 convert weights; blocks 5+ zero g_cnt
// ---------------------------------------------------------------------------
__global__ void prep_zero(const float* __restrict__ Wenc,
                          const float* __restrict__ W1,
                          const float* __restrict__ W2, int N)
{
    int t = blockIdx.x;
    if (t >= 5) {
        int i = (t - 5) * 512 + threadIdx.x;
        if (i < N) g_cnt[i] = 0;
        return;
    }
    __half* dst = (t == 0) ? g_wenc16 : (t <= 2) ? g_w1h[t - 1] : g_w2h[t - 3];
    for (int idx = threadIdx.x; idx < 16384; idx += 512) {
        int row = idx >> 7, col = idx & 127;
        float v;
        if (t == 0)      v = Wenc[row * 128 + col];
        else if (t <= 2) v = W1[(size_t)((t - 1) * 128 + row) * 128 + col];
        else             v = W2[(size_t)row * 256 + (t - 3) * 128 + col];
        dst[row * RSH + col] = __float2half(v);
    }
}

// ---------------------------------------------------------------------------
// Bucket: rec = src(20b) | (a0*8)<<20 | (a1*8)<<26
// ---------------------------------------------------------------------------
__global__ void bucket_kernel(const int* __restrict__ ei,
                              const int* __restrict__ attr, int E)
{
    int e = (blockIdx.x * blockDim.x + threadIdx.x) * 4;
    if (e >= E) return;
    if (e + 4 <= E) {
        int4 s4 = *(const int4*)&ei[e];
        int4 d4 = *(const int4*)&ei[E + e];
        int4 a0 = *(const int4*)&attr[2 * e];
        int4 a1 = *(const int4*)&attr[2 * e + 4];
        int p;
        p = atomicAdd(&g_cnt[d4.x], 1);
        g_sorted[(size_t)d4.x * CAP + p] = s4.x | (a0.x << 23) | (a0.y << 29);
        p = atomicAdd(&g_cnt[d4.y], 1);
        g_sorted[(size_t)d4.y * CAP + p] = s4.y | (a0.z << 23) | (a0.w << 29);
        p = atomicAdd(&g_cnt[d4.z], 1);
        g_sorted[(size_t)d4.z * CAP + p] = s4.z | (a1.x << 23) | (a1.y << 29);
        p = atomicAdd(&g_cnt[d4.w], 1);
        g_sorted[(size_t)d4.w * CAP + p] = s4.w | (a1.z << 23) | (a1.w << 29);
    } else {
        for (; e < E; e++) {
            int src = ei[e];
            int dst = ei[E + e];
            int p = atomicAdd(&g_cnt[dst], 1);
            g_sorted[(size_t)dst * CAP + p] =
                src | (attr[2 * e] << 23) | (attr[2 * e + 1] << 29);
        }
    }
}

// ---------------------------------------------------------------------------
// Kernel 1: g_h16 = (half) prelu(x) @ Wenc^T    (fp16 MMA, 2 CTA/SM)
// ---------------------------------------------------------------------------
#define E_A    0
#define E_B    BUF
#define E_SMEM (2 * BUF)

__global__ __launch_bounds__(512, 2) void enc_mma(
    const float* __restrict__ x, const float* __restrict__ prelu_a, int N)
{
    extern __shared__ char sm[];
    uint32_t smb = smem_u32(sm);
    const int tid = threadIdx.x;
    const int row0 = blockIdx.x << 7;
    const float pav = prelu_a[0];

    for (int i = tid; i < 2176; i += 512)
        cp16(smb + E_B + i * 16, (const char*)g_wenc16 + i * 16);

    for (int c = tid; c < 2048; c += 512) {
        int row = c >> 4, kc = c & 15;
        int gm = row0 + row;
        float v[8];
        if (gm < N) {
            const float4* p = (const float4*)&x[(size_t)gm * 128 + kc * 8];
            float4 a = p[0], b = p[1];
            v[0]=a.x; v[1]=a.y; v[2]=a.z; v[3]=a.w; v[4]=b.x; v[5]=b.y; v[6]=b.z; v[7]=b.w;
#pragma unroll
            for (int i = 0; i < 8; i++) v[i] = (v[i] >= 0.f) ? v[i] : pav * v[i];
        } else {
#pragma unroll
            for (int i = 0; i < 8; i++) v[i] = 0.f;
        }
        *(uint4*)(sm + E_A + row * RS + kc * 16) = cvt_h8(v);
    }
    cp_commit_wait();
    __syncthreads();

    const int wid = tid >> 5, lane = tid & 31;
    const int wm = (wid >> 2) * 32, wn = (wid & 3) * 32;

    float acc[2][4][4];
#pragma unroll
    for (int a = 0; a < 2; a++)
#pragma unroll
        for (int b = 0; b < 4; b++)
#pragma unroll
            for (int q = 0; q < 4; q++) acc[a][b][q] = 0.f;

    gemm_k128_f16(acc, smb + E_A, smb + E_B, wm, wn, lane);

    const int r4 = lane >> 2, c2 = (lane & 3) * 2;
#pragma unroll
    for (int mf = 0; mf < 2; mf++)
#pragma unroll
        for (int nf = 0; nf < 4; nf++) {
            int col = wn + nf * 8 + c2;
            int gm0 = row0 + wm + mf * 16 + r4;
            int gm1 = gm0 + 8;
            float* a4 = acc[mf][nf];
            if (gm0 < N)
                *(__half2*)&g_h16[(size_t)gm0 * 128 + col] = __floats2half2_rn(a4[0], a4[1]);
            if (gm1 < N)
                *(__half2*)&g_h16[(size_t)gm1 * 128 + col] = __floats2half2_rn(a4[2], a4[3]);
        }
}

// ---------------------------------------------------------------------------
// Gather: 16 lanes per dst (2 dsts/warp), 8 halves per lane.
// Edge embeddings handled by packed combo histogram + count*emb epilogue.
// ---------------------------------------------------------------------------
__global__ __launch_bounds__(512) void gather_kernel(
    const float* __restrict__ emb1, const float* __restrict__ emb2, int N)
{
    __shared__ float e1s[6 * 128];
    __shared__ float e2s[3 * 128];
    __shared__ float se[128];
    int tid = threadIdx.x;
    for (int idx = tid; idx < 6 * 128; idx += 512) e1s[idx] = emb1[idx];
    if (tid < 3 * 128) e2s[tid] = emb2[tid];
    __syncthreads();  // e1s/e2s ready (se derives from them)
    if (tid < 128) se[tid] = e1s[4 * 128 + tid] + e2s[tid];
    __syncthreads();

    const int wid = tid >> 5, lane = tid & 31;
    const int half_ = lane >> 4;
    const int l16 = lane & 15;
    const int fb = l16 * 8;
    int d = blockIdx.x * 32 + wid * 2 + half_;
    if (d >= N) return;

    float acc[8];
    {
        uint4 hw = *(const uint4*)&g_h16[(size_t)d * 128 + fb];
        const __half2* hp = (const __half2*)&hw;
        const float4 s0 = *(const float4*)&se[fb];
        const float4 s1 = *(const float4*)&se[fb + 4];
        float2 f0 = __half22float2(hp[0]), f1 = __half22float2(hp[1]);
        float2 f2 = __half22float2(hp[2]), f3 = __half22float2(hp[3]);
        acc[0] = f0.x + s0.x; acc[1] = f0.y + s0.y;
        acc[2] = f1.x + s0.z; acc[3] = f1.y + s0.w;
        acc[4] = f2.x + s1.x; acc[5] = f2.y + s1.y;
        acc[6] = f3.x + s1.z; acc[7] = f3.y + s1.w;
    }

    unsigned long long sumA = 0;  // 6 x 8-bit counts of a0
    uint32_t sumB = 0;            // 3 x 8-bit counts of a1
    const int sb = d * CAP;
    const int c = g_cnt[d];
    int i = 0;
    for (; i + 2 <= c; i += 2) {
        int r0 = g_sorted[sb + i];
        int r1 = g_sorted[sb + i + 1];
        uint4 w0 = *(const uint4*)&g_h16[(size_t)(r0 & 0xFFFFF) * 128 + fb];
        uint4 w1 = *(const uint4*)&g_h16[(size_t)(r1 & 0xFFFFF) * 128 + fb];
        sumA += 1ull << (((uint32_t)r0 >> 20) & 0x38);
        sumB += 1u << ((uint32_t)r0 >> 26);
        sumA += 1ull << (((uint32_t)r1 >> 20) & 0x38);
        sumB += 1u << ((uint32_t)r1 >> 26);
        const __half2* p0 = (const __half2*)&w0;
        const __half2* p1 = (const __half2*)&w1;
        float2 m;
        m = __half22float2(p0[0]); acc[0] += m.x; acc[1] += m.y;
        m = __half22float2(p0[1]); acc[2] += m.x; acc[3] += m.y;
        m = __half22float2(p0[2]); acc[4] += m.x; acc[5] += m.y;
        m = __half22float2(p0[3]); acc[6] += m.x; acc[7] += m.y;
        m = __half22float2(p1[0]); acc[0] += m.x; acc[1] += m.y;
        m = __half22float2(p1[1]); acc[2] += m.x; acc[3] += m.y;
        m = __half22float2(p1[2]); acc[4] += m.x; acc[5] += m.y;
        m = __half22float2(p1[3]); acc[6] += m.x; acc[7] += m.y;
    }
    if (i < c) {
        int r0 = g_sorted[sb + i];
        uint4 w0 = *(const uint4*)&g_h16[(size_t)(r0 & 0xFFFFF) * 128 + fb];
        sumA += 1ull << (((uint32_t)r0 >> 20) & 0x38);
        sumB += 1u << ((uint32_t)r0 >> 26);
        const __half2* p0 = (const __half2*)&w0;
        float2 m;
        m = __half22float2(p0[0]); acc[0] += m.x; acc[1] += m.y;
        m = __half22float2(p0[1]); acc[2] += m.x; acc[3] += m.y;
        m = __half22float2(p0[2]); acc[4] += m.x; acc[5] += m.y;
        m = __half22float2(p0[3]); acc[6] += m.x; acc[7] += m.y;
    }

    // epilogue: acc += sum_k cntA[k]*emb1[k] + sum_j cntB[j]*emb2[j]
#pragma unroll
    for (int k = 0; k < 6; k++) {
        float cf = (float)((sumA >> (k * 8)) & 0xFF);
        const float4 v0 = *(const float4*)&e1s[k * 128 + fb];
        const float4 v1 = *(const float4*)&e1s[k * 128 + fb + 4];
        acc[0] += cf * v0.x; acc[1] += cf * v0.y;
        acc[2] += cf * v0.z; acc[3] += cf * v0.w;
        acc[4] += cf * v1.x; acc[5] += cf * v1.y;
        acc[6] += cf * v1.z; acc[7] += cf * v1.w;
    }
#pragma unroll
    for (int j = 0; j < 3; j++) {
        float cf = (float)((sumB >> (j * 8)) & 0xFF);
        const float4 v0 = *(const float4*)&e2s[j * 128 + fb];
        const float4 v1 = *(const float4*)&e2s[j * 128 + fb + 4];
        acc[0] += cf * v0.x; acc[1] += cf * v0.y;
        acc[2] += cf * v0.z; acc[3] += cf * v0.w;
        acc[4] += cf * v1.x; acc[5] += cf * v1.y;
        acc[6] += cf * v1.z; acc[7] += cf * v1.w;
    }
    *(uint4*)&g_agg16[(size_t)d * 128 + fb] = cvt_h8(acc);
}

// ---------------------------------------------------------------------------
// Kernel 3: fused MLP, fp16 single-term, 2 CTA/SM
// ---------------------------------------------------------------------------
#define M_B1   0
#define M_B2   1024
#define M_A    2048
#define M_B    (M_A + BUF)
#define M_H    (M_B + BUF)
#define M_SMEM (M_H + BUF)   // 106496

__global__ __launch_bounds__(512, 2) void mlp_mma(
    const float* __restrict__ b1, const float* __restrict__ b2,
    float* __restrict__ out, int N)
{
    extern __shared__ char sm[];
    uint32_t smb = smem_u32(sm);
    const int tid = threadIdx.x;
    const int row0 = blockIdx.x << 7;
    float* b1s = (float*)(sm + M_B1);
    float* b2s = (float*)(sm + M_B2);
    if (tid < 256) b1s[tid] = b1[tid];
    else if (tid < 384) b2s[tid - 256] = b2[tid - 256];

    for (int i = tid; i < 2048; i += 512) {
        int row = i >> 4, q = i & 15;
        int gm = row0 + row;
        if (gm >= N) gm = N - 1;
        cp16(smb + M_A + row * RS + q * 16, &g_agg16[(size_t)gm * 128 + q * 8]);
    }

    const int wid = tid >> 5, lane = tid & 31;
    const int wm = (wid >> 2) * 32, wn = (wid & 3) * 32;
    const int r4 = lane >> 2, c2 = (lane & 3) * 2;

    float acc2[2][4][4];
#pragma unroll
    for (int a = 0; a < 2; a++)
#pragma unroll
        for (int b = 0; b < 4; b++)
#pragma unroll
            for (int q = 0; q < 4; q++) acc2[a][b][q] = 0.f;

    for (int jc = 0; jc < 2; jc++) {
        for (int i = tid; i < 2176; i += 512)
            cp16(smb + M_B + i * 16, (const char*)g_w1h[jc] + i * 16);
        cp_commit_wait();
        __syncthreads();

        float acc1[2][4][4];
#pragma unroll
        for (int a = 0; a < 2; a++)
#pragma unroll
            for (int b = 0; b < 4; b++)
#pragma unroll
                for (int q = 0; q < 4; q++) acc1[a][b][q] = 0.f;
        gemm_k128_f16(acc1, smb + M_A, smb + M_B, wm, wn, lane);
        __syncthreads();

        for (int i = tid; i < 2176; i += 512)
            cp16(smb + M_B + i * 16, (const char*)g_w2h[jc] + i * 16);
#pragma unroll
        for (int mf = 0; mf < 2; mf++)
#pragma unroll
            for (int nf = 0; nf < 4; nf++) {
                int jcol = wn + nf * 8 + c2;
                float bb0 = b1s[jc * 128 + jcol], bb1 = b1s[jc * 128 + jcol + 1];
                float* a4 = acc1[mf][nf];
#pragma unroll
                for (int half = 0; half < 2; half++) {
                    float t0 = a4[2 * half] + bb0, t1 = a4[2 * half + 1] + bb1;
                    t0 = (t0 > 0.f) ? t0 : 0.f;
                    t1 = (t1 > 0.f) ? t1 : 0.f;
                    __half2 hh = __floats2half2_rn(t0, t1);
                    int mrow = wm + mf * 16 + r4 + half * 8;
                    *(uint32_t*)(sm + M_H + mrow * RS + jcol * 2) =
                        *reinterpret_cast<uint32_t*>(&hh);
                }
            }
        cp_commit_wait();
        __syncthreads();

        gemm_k128_f16(acc2, smb + M_H, smb + M_B, wm, wn, lane);
        __syncthreads();
    }

#pragma unroll
    for (int mf = 0; mf < 2; mf++)
#pragma unroll
        for (int nf = 0; nf < 4; nf++) {
            int col = wn + nf * 8 + c2;
            float2 bb = {b2s[col], b2s[col + 1]};
            int gm0 = row0 + wm + mf * 16 + r4;
            int gm1 = gm0 + 8;
            float* a4 = acc2[mf][nf];
            if (gm0 < N)
                *(float2*)&out[(size_t)gm0 * 128 + col] = make_float2(a4[0] + bb.x, a4[1] + bb.y);
            if (gm1 < N)
                *(float2*)&out[(size_t)gm1 * 128 + col] = make_float2(a4[2] + bb.x, a4[3] + bb.y);
        }
}

// ---------------------------------------------------------------------------
extern "C" void kernel_launch(void* const* d_in, const int* in_sizes, int n_in,
                              void* d_out, int out_size)
{
    const float* x    = (const float*)d_in[0];
    const int*   ei   = (const int*)  d_in[1];
    const int*   attr = (const int*)  d_in[2];
    const float* pa   = (const float*)d_in[3];
    const float* Wenc = (const float*)d_in[4];
    const float* emb1 = (const float*)d_in[5];
    const float* emb2 = (const float*)d_in[6];
    const float* W1   = (const float*)d_in[7];
    const float* b1   = (const float*)d_in[8];
    const float* W2   = (const float*)d_in[9];
    const float* b2   = (const float*)d_in[10];

    int N = in_sizes[0] / 128;
    int E = in_sizes[1] / 2;

    cudaFuncSetAttribute(enc_mma, cudaFuncAttributeMaxDynamicSharedMemorySize, E_SMEM);
    cudaFuncSetAttribute(mlp_mma, cudaFuncAttributeMaxDynamicSharedMemorySize, M_SMEM);

    int mblocks = (N + 127) / 128;

    prep_zero<<<5 + (N + 511) / 512, 512>>>(Wenc, W1, W2, N);
    bucket_kernel<<<(E / 4 + 255) / 256, 256>>>(ei, attr, E);
    enc_mma<<<mblocks, 512, E_SMEM>>>(x, pa, N);
    gather_kernel<<<(N + 31) / 32, 512>>>(emb1, emb2, N);
    mlp_mma<<<mblocks, 512, M_SMEM>>>(b1, b2, (float*)d_out, N);
}

// round 14
// speedup vs baseline: 1.0467x; 1.0467x over previous
#include <cuda_runtime.h>
#include <cuda_fp16.h>
#include <cstdint>

#define NMAX 100000
#define CAP 64         // per-dst bucket capacity (max degree ~40 for Poisson(16))
#define RS 272         // smem row stride bytes (136 halves) -> conflict-free ldmatrix
#define RSH 136
#define BUF 34816      // 128 * RS

__device__ __align__(256) __half g_h16[(size_t)NMAX * 128];
__device__ __align__(256) __half g_agg16[(size_t)NMAX * 128];
__device__ __align__(256) __half g_wenc16[128 * RSH];
__device__ __align__(256) __half g_w1h[2][128 * RSH];
__device__ __align__(256) __half g_w2h[2][128 * RSH];
__device__ int g_cnt[NMAX];
__device__ int g_sorted[(size_t)NMAX * CAP];

// ---------------------------------------------------------------------------
__device__ __forceinline__ uint32_t smem_u32(const void* p) {
    uint32_t a;
    asm("{ .reg .u64 t; cvta.to.shared.u64 t, %1; cvt.u32.u64 %0, t; }"
        : "=r"(a) : "l"(p));
    return a;
}
__device__ __forceinline__ void ldsm4(uint32_t* r, uint32_t addr) {
    asm volatile("ldmatrix.sync.aligned.m8n8.x4.shared.b16 {%0,%1,%2,%3}, [%4];"
                 : "=r"(r[0]), "=r"(r[1]), "=r"(r[2]), "=r"(r[3]) : "r"(addr));
}
__device__ __forceinline__ void mma_f16(float* c, const uint32_t* a, const uint32_t* b) {
    asm volatile(
        "mma.sync.aligned.m16n8k16.row.col.f32.f16.f16.f32 "
        "{%0,%1,%2,%3}, {%4,%5,%6,%7}, {%8,%9}, {%0,%1,%2,%3};"
        : "+f"(c[0]), "+f"(c[1]), "+f"(c[2]), "+f"(c[3])
        : "r"(a[0]), "r"(a[1]), "r"(a[2]), "r"(a[3]), "r"(b[0]), "r"(b[1]));
}
__device__ __forceinline__ void cp16(uint32_t smem_dst, const void* gsrc) {
    asm volatile("cp.async.cg.shared.global [%0], [%1], 16;"
                 :: "r"(smem_dst), "l"(gsrc));
}
__device__ __forceinline__ void cp_commit_wait() {
    asm volatile("cp.async.commit_group;");
    asm volatile("cp.async.wait_group 0;" ::: "memory");
}
__device__ __forceinline__ uint4 cvt_h8(const float* v) {
    __half2 h0 = __floats2half2_rn(v[0], v[1]);
    __half2 h1 = __floats2half2_rn(v[2], v[3]);
    __half2 h2 = __floats2half2_rn(v[4], v[5]);
    __half2 h3 = __floats2half2_rn(v[6], v[7]);
    return make_uint4(*reinterpret_cast<uint32_t*>(&h0),
                      *reinterpret_cast<uint32_t*>(&h1),
                      *reinterpret_cast<uint32_t*>(&h2),
                      *reinterpret_cast<uint32_t*>(&h3));
}

// single-term fp16 K=128 GEMM, 16-warp layout: acc[2][4][4], 32x32 warp tile
__device__ __forceinline__ void gemm_k128_f16(
    float acc[2][4][4], uint32_t sA, uint32_t sB, int wm, int wn, int lane)
{
    const int arow = lane & 15;
    const int akc  = (lane >> 4) * 8;
    const int bn   = (lane & 7) + (lane >> 4) * 8;
    const int bk   = ((lane >> 3) & 1) * 8;
#pragma unroll
    for (int ks = 0; ks < 8; ks++) {
        const int k0 = ks * 16;
        uint32_t a[2][4];
#pragma unroll
        for (int mf = 0; mf < 2; mf++)
            ldsm4(a[mf], sA + (uint32_t)(wm + mf * 16 + arow) * RS + (uint32_t)(k0 + akc) * 2);
        uint32_t b[4][2];
#pragma unroll
        for (int g = 0; g < 2; g++) {
            uint32_t r[4];
            ldsm4(r, sB + (uint32_t)(wn + g * 16 + bn) * RS + (uint32_t)(k0 + bk) * 2);
            b[2 * g][0] = r[0]; b[2 * g][1] = r[1];
            b[2 * g + 1][0] = r[2]; b[2 * g + 1][1] = r[3];
        }
#pragma unroll
        for (int mf = 0; mf < 2; mf++)
#pragma unroll
            for (int nf = 0; nf < 4; nf++)
                mma_f16(acc[mf][nf], a[mf], b[nf]);
    }
}

// ---------------------------------------------------------------------------
// prep+zero: blocks 0-4 convert weights; blocks 5+ zero g_cnt
// ---------------------------------------------------------------------------
__global__ void prep_zero(const float* __restrict__ Wenc,
                          const float* __restrict__ W1,
                          const float* __restrict__ W2, int N)
{
    int t = blockIdx.x;
    if (t >= 5) {
        int i = (t - 5) * 512 + threadIdx.x;
        if (i < N) g_cnt[i] = 0;
        return;
    }
    __half* dst = (t == 0) ? g_wenc16 : (t <= 2) ? g_w1h[t - 1] : g_w2h[t - 3];
    for (int idx = threadIdx.x; idx < 16384; idx += 512) {
        int row = idx >> 7, col = idx & 127;
        float v;
        if (t == 0)      v = Wenc[row * 128 + col];
        else if (t <= 2) v = W1[(size_t)((t - 1) * 128 + row) * 128 + col];
        else             v = W2[(size_t)row * 256 + (t - 3) * 128 + col];
        dst[row * RSH + col] = __float2half(v);
    }
}

// ---------------------------------------------------------------------------
// Bucket: rec = src(20b) | (a0*8)<<20 | (a1*8)<<26
// ---------------------------------------------------------------------------
__global__ void bucket_kernel(const int* __restrict__ ei,
                              const int* __restrict__ attr, int E)
{
    int e = (blockIdx.x * blockDim.x + threadIdx.x) * 4;
    if (e >= E) return;
    if (e + 4 <= E) {
        int4 s4 = *(const int4*)&ei[e];
        int4 d4 = *(const int4*)&ei[E + e];
        int4 a0 = *(const int4*)&attr[2 * e];
        int4 a1 = *(const int4*)&attr[2 * e + 4];
        int p;
        p = atomicAdd(&g_cnt[d4.x], 1);
        g_sorted[(size_t)d4.x * CAP + p] = s4.x | (a0.x << 23) | (a0.y << 29);
        p = atomicAdd(&g_cnt[d4.y], 1);
        g_sorted[(size_t)d4.y * CAP + p] = s4.y | (a0.z << 23) | (a0.w << 29);
        p = atomicAdd(&g_cnt[d4.z], 1);
        g_sorted[(size_t)d4.z * CAP + p] = s4.z | (a1.x << 23) | (a1.y << 29);
        p = atomicAdd(&g_cnt[d4.w], 1);
        g_sorted[(size_t)d4.w * CAP + p] = s4.w | (a1.z << 23) | (a1.w << 29);
    } else {
        for (; e < E; e++) {
            int src = ei[e];
            int dst = ei[E + e];
            int p = atomicAdd(&g_cnt[dst], 1);
            g_sorted[(size_t)dst * CAP + p] =
                src | (attr[2 * e] << 23) | (attr[2 * e + 1] << 29);
        }
    }
}

// ---------------------------------------------------------------------------
// Kernel 1: g_h16 = (half) prelu(x) @ Wenc^T    (fp16 MMA, 2 CTA/SM)
// ---------------------------------------------------------------------------
#define E_A    0
#define E_B    BUF
#define E_SMEM (2 * BUF)

__global__ __launch_bounds__(512, 2) void enc_mma(
    const float* __restrict__ x, const float* __restrict__ prelu_a, int N)
{
    extern __shared__ char sm[];
    uint32_t smb = smem_u32(sm);
    const int tid = threadIdx.x;
    const int row0 = blockIdx.x << 7;
    const float pav = prelu_a[0];

    for (int i = tid; i < 2176; i += 512)
        cp16(smb + E_B + i * 16, (const char*)g_wenc16 + i * 16);

    for (int c = tid; c < 2048; c += 512) {
        int row = c >> 4, kc = c & 15;
        int gm = row0 + row;
        float v[8];
        if (gm < N) {
            const float4* p = (const float4*)&x[(size_t)gm * 128 + kc * 8];
            float4 a = p[0], b = p[1];
            v[0]=a.x; v[1]=a.y; v[2]=a.z; v[3]=a.w; v[4]=b.x; v[5]=b.y; v[6]=b.z; v[7]=b.w;
#pragma unroll
            for (int i = 0; i < 8; i++) v[i] = (v[i] >= 0.f) ? v[i] : pav * v[i];
        } else {
#pragma unroll
            for (int i = 0; i < 8; i++) v[i] = 0.f;
        }
        *(uint4*)(sm + E_A + row * RS + kc * 16) = cvt_h8(v);
    }
    cp_commit_wait();
    __syncthreads();

    const int wid = tid >> 5, lane = tid & 31;
    const int wm = (wid >> 2) * 32, wn = (wid & 3) * 32;

    float acc[2][4][4];
#pragma unroll
    for (int a = 0; a < 2; a++)
#pragma unroll
        for (int b = 0; b < 4; b++)
#pragma unroll
            for (int q = 0; q < 4; q++) acc[a][b][q] = 0.f;

    gemm_k128_f16(acc, smb + E_A, smb + E_B, wm, wn, lane);

    const int r4 = lane >> 2, c2 = (lane & 3) * 2;
#pragma unroll
    for (int mf = 0; mf < 2; mf++)
#pragma unroll
        for (int nf = 0; nf < 4; nf++) {
            int col = wn + nf * 8 + c2;
            int gm0 = row0 + wm + mf * 16 + r4;
            int gm1 = gm0 + 8;
            float* a4 = acc[mf][nf];
            if (gm0 < N)
                *(__half2*)&g_h16[(size_t)gm0 * 128 + col] = __floats2half2_rn(a4[0], a4[1]);
            if (gm1 < N)
                *(__half2*)&g_h16[(size_t)gm1 * 128 + col] = __floats2half2_rn(a4[2], a4[3]);
        }
}

// ---------------------------------------------------------------------------
// Gather: 16 lanes per dst (2 dsts/warp), 8 halves per lane.
// int4 rec loads (4 edges/iter), fp16 pair-accumulation, histogram epilogue.
// ---------------------------------------------------------------------------
__global__ __launch_bounds__(512) void gather_kernel(
    const float* __restrict__ emb1, const float* __restrict__ emb2, int N)
{
    __shared__ float e1s[6 * 128];
    __shared__ float e2s[3 * 128];
    __shared__ float se[128];
    int tid = threadIdx.x;
    for (int idx = tid; idx < 6 * 128; idx += 512) e1s[idx] = emb1[idx];
    if (tid < 3 * 128) e2s[tid] = emb2[tid];
    __syncthreads();  // e1s/e2s ready (se derives from them)
    if (tid < 128) se[tid] = e1s[4 * 128 + tid] + e2s[tid];
    __syncthreads();

    const int wid = tid >> 5, lane = tid & 31;
    const int half_ = lane >> 4;
    const int l16 = lane & 15;
    const int fb = l16 * 8;
    int d = blockIdx.x * 32 + wid * 2 + half_;
    if (d >= N) return;

    float acc[8];
    {
        uint4 hw = *(const uint4*)&g_h16[(size_t)d * 128 + fb];
        const __half2* hp = (const __half2*)&hw;
        const float4 s0 = *(const float4*)&se[fb];
        const float4 s1 = *(const float4*)&se[fb + 4];
        float2 f0 = __half22float2(hp[0]), f1 = __half22float2(hp[1]);
        float2 f2 = __half22float2(hp[2]), f3 = __half22float2(hp[3]);
        acc[0] = f0.x + s0.x; acc[1] = f0.y + s0.y;
        acc[2] = f1.x + s0.z; acc[3] = f1.y + s0.w;
        acc[4] = f2.x + s1.x; acc[5] = f2.y + s1.y;
        acc[6] = f3.x + s1.z; acc[7] = f3.y + s1.w;
    }

    unsigned long long sumA = 0;  // 6 x 8-bit counts of a0
    uint32_t sumB = 0;            // 3 x 8-bit counts of a1
    const int sb = d * CAP;       // 256B-aligned bucket base
    const int c = g_cnt[d];
    int i = 0;
    // 4 edges per iteration: one int4 rec load, fp16 pair-sums
    for (; i + 4 <= c; i += 4) {
        int4 r = *(const int4*)&g_sorted[sb + i];
        uint4 w0 = *(const uint4*)&g_h16[(size_t)((uint32_t)r.x & 0xFFFFF) * 128 + fb];
        uint4 w1 = *(const uint4*)&g_h16[(size_t)((uint32_t)r.y & 0xFFFFF) * 128 + fb];
        uint4 w2 = *(const uint4*)&g_h16[(size_t)((uint32_t)r.z & 0xFFFFF) * 128 + fb];
        uint4 w3 = *(const uint4*)&g_h16[(size_t)((uint32_t)r.w & 0xFFFFF) * 128 + fb];
        sumA += (1ull << (((uint32_t)r.x >> 20) & 0x38))
              + (1ull << (((uint32_t)r.y >> 20) & 0x38))
              + (1ull << (((uint32_t)r.z >> 20) & 0x38))
              + (1ull << (((uint32_t)r.w >> 20) & 0x38));
        sumB += (1u << ((uint32_t)r.x >> 26)) + (1u << ((uint32_t)r.y >> 26))
              + (1u << ((uint32_t)r.z >> 26)) + (1u << ((uint32_t)r.w >> 26));
        const __half2* p0 = (const __half2*)&w0;
        const __half2* p1 = (const __half2*)&w1;
        const __half2* p2 = (const __half2*)&w2;
        const __half2* p3 = (const __half2*)&w3;
#pragma unroll
        for (int q = 0; q < 4; q++) {
            __half2 sA2 = __hadd2(p0[q], p1[q]);   // pair-sum in fp16
            __half2 sB2 = __hadd2(p2[q], p3[q]);
            float2 fa = __half22float2(sA2);
            float2 fc = __half22float2(sB2);
            acc[2 * q]     += fa.x + fc.x;
            acc[2 * q + 1] += fa.y + fc.y;
        }
    }
    // tail (0-3 edges), exact fp32 path
    for (; i < c; i++) {
        int r0 = g_sorted[sb + i];
        uint4 w0 = *(const uint4*)&g_h16[(size_t)((uint32_t)r0 & 0xFFFFF) * 128 + fb];
        sumA += 1ull << (((uint32_t)r0 >> 20) & 0x38);
        sumB += 1u << ((uint32_t)r0 >> 26);
        const __half2* p0 = (const __half2*)&w0;
        float2 m;
        m = __half22float2(p0[0]); acc[0] += m.x; acc[1] += m.y;
        m = __half22float2(p0[1]); acc[2] += m.x; acc[3] += m.y;
        m = __half22float2(p0[2]); acc[4] += m.x; acc[5] += m.y;
        m = __half22float2(p0[3]); acc[6] += m.x; acc[7] += m.y;
    }

    // epilogue: acc += sum_k cntA[k]*emb1[k] + sum_j cntB[j]*emb2[j]
#pragma unroll
    for (int k = 0; k < 6; k++) {
        float cf = (float)((sumA >> (k * 8)) & 0xFF);
        const float4 v0 = *(const float4*)&e1s[k * 128 + fb];
        const float4 v1 = *(const float4*)&e1s[k * 128 + fb + 4];
        acc[0] += cf * v0.x; acc[1] += cf * v0.y;
        acc[2] += cf * v0.z; acc[3] += cf * v0.w;
        acc[4] += cf * v1.x; acc[5] += cf * v1.y;
        acc[6] += cf * v1.z; acc[7] += cf * v1.w;
    }
#pragma unroll
    for (int j = 0; j < 3; j++) {
        float cf = (float)((sumB >> (j * 8)) & 0xFF);
        const float4 v0 = *(const float4*)&e2s[j * 128 + fb];
        const float4 v1 = *(const float4*)&e2s[j * 128 + fb + 4];
        acc[0] += cf * v0.x; acc[1] += cf * v0.y;
        acc[2] += cf * v0.z; acc[3] += cf * v0.w;
        acc[4] += cf * v1.x; acc[5] += cf * v1.y;
        acc[6] += cf * v1.z; acc[7] += cf * v1.w;
    }
    *(uint4*)&g_agg16[(size_t)d * 128 + fb] = cvt_h8(acc);
}

// ---------------------------------------------------------------------------
// Kernel 3: fused MLP, fp16 single-term, 2 CTA/SM
// ---------------------------------------------------------------------------
#define M_B1   0
#define M_B2   1024
#define M_A    2048
#define M_B    (M_A + BUF)
#define M_H    (M_B + BUF)
#define M_SMEM (M_H + BUF)   // 106496

__global__ __launch_bounds__(512, 2) void mlp_mma(
    const float* __restrict__ b1, const float* __restrict__ b2,
    float* __restrict__ out, int N)
{
    extern __shared__ char sm[];
    uint32_t smb = smem_u32(sm);
    const int tid = threadIdx.x;
    const int row0 = blockIdx.x << 7;
    float* b1s = (float*)(sm + M_B1);
    float* b2s = (float*)(sm + M_B2);
    if (tid < 256) b1s[tid] = b1[tid];
    else if (tid < 384) b2s[tid - 256] = b2[tid - 256];

    for (int i = tid; i < 2048; i += 512) {
        int row = i >> 4, q = i & 15;
        int gm = row0 + row;
        if (gm >= N) gm = N - 1;
        cp16(smb + M_A + row * RS + q * 16, &g_agg16[(size_t)gm * 128 + q * 8]);
    }

    const int wid = tid >> 5, lane = tid & 31;
    const int wm = (wid >> 2) * 32, wn = (wid & 3) * 32;
    const int r4 = lane >> 2, c2 = (lane & 3) * 2;

    float acc2[2][4][4];
#pragma unroll
    for (int a = 0; a < 2; a++)
#pragma unroll
        for (int b = 0; b < 4; b++)
#pragma unroll
            for (int q = 0; q < 4; q++) acc2[a][b][q] = 0.f;

    for (int jc = 0; jc < 2; jc++) {
        for (int i = tid; i < 2176; i += 512)
            cp16(smb + M_B + i * 16, (const char*)g_w1h[jc] + i * 16);
        cp_commit_wait();
        __syncthreads();

        float acc1[2][4][4];
#pragma unroll
        for (int a = 0; a < 2; a++)
#pragma unroll
            for (int b = 0; b < 4; b++)
#pragma unroll
                for (int q = 0; q < 4; q++) acc1[a][b][q] = 0.f;
        gemm_k128_f16(acc1, smb + M_A, smb + M_B, wm, wn, lane);
        __syncthreads();

        for (int i = tid; i < 2176; i += 512)
            cp16(smb + M_B + i * 16, (const char*)g_w2h[jc] + i * 16);
#pragma unroll
        for (int mf = 0; mf < 2; mf++)
#pragma unroll
            for (int nf = 0; nf < 4; nf++) {
                int jcol = wn + nf * 8 + c2;
                float bb0 = b1s[jc * 128 + jcol], bb1 = b1s[jc * 128 + jcol + 1];
                float* a4 = acc1[mf][nf];
#pragma unroll
                for (int half = 0; half < 2; half++) {
                    float t0 = a4[2 * half] + bb0, t1 = a4[2 * half + 1] + bb1;
                    t0 = (t0 > 0.f) ? t0 : 0.f;
                    t1 = (t1 > 0.f) ? t1 : 0.f;
                    __half2 hh = __floats2half2_rn(t0, t1);
                    int mrow = wm + mf * 16 + r4 + half * 8;
                    *(uint32_t*)(sm + M_H + mrow * RS + jcol * 2) =
                        *reinterpret_cast<uint32_t*>(&hh);
                }
            }
        cp_commit_wait();
        __syncthreads();

        gemm_k128_f16(acc2, smb + M_H, smb + M_B, wm, wn, lane);
        __syncthreads();
    }

#pragma unroll
    for (int mf = 0; mf < 2; mf++)
#pragma unroll
        for (int nf = 0; nf < 4; nf++) {
            int col = wn + nf * 8 + c2;
            float2 bb = {b2s[col], b2s[col + 1]};
            int gm0 = row0 + wm + mf * 16 + r4;
            int gm1 = gm0 + 8;
            float* a4 = acc2[mf][nf];
            if (gm0 < N)
                *(float2*)&out[(size_t)gm0 * 128 + col] = make_float2(a4[0] + bb.x, a4[1] + bb.y);
            if (gm1 < N)
                *(float2*)&out[(size_t)gm1 * 128 + col] = make_float2(a4[2] + bb.x, a4[3] + bb.y);
        }
}

// ---------------------------------------------------------------------------
extern "C" void kernel_launch(void* const* d_in, const int* in_sizes, int n_in,
                              void* d_out, int out_size)
{
    const float* x    = (const float*)d_in[0];
    const int*   ei   = (const int*)  d_in[1];
    const int*   attr = (const int*)  d_in[2];
    const float* pa   = (const float*)d_in[3];
    const float* Wenc = (const float*)d_in[4];
    const float* emb1 = (const float*)d_in[5];
    const float* emb2 = (const float*)d_in[6];
    const float* W1   = (const float*)d_in[7];
    const float* b1   = (const float*)d_in[8];
    const float* W2   = (const float*)d_in[9];
    const float* b2   = (const float*)d_in[10];

    int N = in_sizes[0] / 128;
    int E = in_sizes[1] / 2;

    cudaFuncSetAttribute(enc_mma, cudaFuncAttributeMaxDynamicSharedMemorySize, E_SMEM);
    cudaFuncSetAttribute(mlp_mma, cudaFuncAttributeMaxDynamicSharedMemorySize, M_SMEM);

    int mblocks = (N + 127) / 128;

    prep_zero<<<5 + (N + 511) / 512, 512>>>(Wenc, W1, W2, N);
    bucket_kernel<<<(E / 4 + 255) / 256, 256>>>(ei, attr, E);
    enc_mma<<<mblocks, 512, E_SMEM>>>(x, pa, N);
    gather_kernel<<<(N + 31) / 32, 512>>>(emb1, emb2, N);
    mlp_mma<<<mblocks, 512, M_SMEM>>>(b1, b2, (float*)d_out, N);
}